// round 3
// baseline (speedup 1.0000x reference)
#include <cuda_runtime.h>
#include <math.h>

// B=8, N=64, D=64, E=32. Block = one (b, i_node). Fused:
//   agg[b,i,:] = sum_{jn,j} mask*relu(edges@W_e + b_e)*nodes  then 2-step GRU.
// Inner GEMM uses packed fma.rn.f32x2 (FFMA2): 2 fp32 FMAs per fma-pipe slot.
// A (edges) lives in smem pre-duplicated as float2(v,v); B (W_e) is read
// straight from global (L1/L2 resident) -> chunk loop is barrier-free.

typedef unsigned long long u64;

__device__ __forceinline__ u64 ffma2(u64 a, u64 b, u64 c) {
    u64 d;
    asm("fma.rn.f32x2 %0, %1, %2, %3;" : "=l"(d) : "l"(a), "l"(b), "l"(c));
    return d;
}
__device__ __forceinline__ void unpack2(u64 v, float& lo, float& hi) {
    asm("mov.b64 {%0, %1}, %2;" : "=f"(lo), "=f"(hi) : "l"(v));
}

__global__ __launch_bounds__(256, 2) void mp_fused_kernel(
    const float* __restrict__ nodes,   // (8,64,64)
    const float* __restrict__ edges,   // (8,4096,32)
    const float* __restrict__ mask,    // (8,4096,1)
    const float* __restrict__ W_e,     // (32,4096)
    const float* __restrict__ b_e,     // (4096,)
    const float* __restrict__ Kmat,    // (64,192)
    const float* __restrict__ Rmat,    // (64,192)
    const float* __restrict__ gbias,   // (2,192)
    float* __restrict__ out)           // (8,64,64)
{
    __shared__ float2 edges_dup[32][64];  // [k][edge], value duplicated (16KB)
    __shared__ float  wt_sh[64][64];      // mask[e]*nodes[b][j_node][j] (16KB)
    __shared__ float  xrow[64];
    __shared__ float  aggs[64];
    __shared__ float  xk1[192], h1[64], xk2[192], hk2[192];

    const int blk   = blockIdx.x;
    const int b     = blk >> 6;
    const int inode = blk & 63;
    const int t     = threadIdx.x;
    const int lane  = t & 31;
    const int warp  = t >> 5;

    // ---- edges (64 x 32) -> transposed + duplicated shared ----
    {
        const float* ebase = edges + ((size_t)b * 4096 + (size_t)inode * 64) * 32;
        for (int i = t; i < 64 * 8; i += 256) {   // float4 granules
            int e = i >> 3;
            int q = i & 7;
            float4 v = *(const float4*)(ebase + e * 32 + q * 4);
            edges_dup[q * 4 + 0][e] = make_float2(v.x, v.x);
            edges_dup[q * 4 + 1][e] = make_float2(v.y, v.y);
            edges_dup[q * 4 + 2][e] = make_float2(v.z, v.z);
            edges_dup[q * 4 + 3][e] = make_float2(v.w, v.w);
        }
    }
    // ---- wt_sh = mask * nodes, xrow, zero aggs ----
    {
        const float* nb = nodes + (size_t)b * 64 * 64;
        const float* mb = mask  + (size_t)b * 4096 + (size_t)inode * 64;
        for (int i = t; i < 64 * 16; i += 256) {  // float4 granules
            int r = i >> 4, q = i & 15;
            float m = mb[r];
            float4 v = *(const float4*)(nb + r * 64 + q * 4);
            float4 w; w.x = v.x * m; w.y = v.y * m; w.z = v.z * m; w.w = v.w * m;
            *(float4*)&wt_sh[r][q * 4] = w;
        }
        if (t < 16) {
            float4 v = *(const float4*)(nb + inode * 64 + t * 4);
            *(float4*)&xrow[t * 4] = v;
        }
        if (t < 64) aggs[t] = 0.0f;
    }
    __syncthreads();

    const int r0 = warp * 8;          // 8 edge-rows per thread
    const int c0 = lane * 8;          // 8 cols per thread, 256 cols per iter
    const float* wcol = W_e + c0;

    for (int it = 0; it < 16; it++) {
        u64 acc[8][4];
        #pragma unroll
        for (int i = 0; i < 8; i++)
            #pragma unroll
            for (int j = 0; j < 4; j++) acc[i][j] = 0ull;

        const float* wp = wcol + it * 256;

        #pragma unroll
        for (int k = 0; k < 32; k++) {
            ulonglong2 A01 = *(const ulonglong2*)&edges_dup[k][r0];
            ulonglong2 A23 = *(const ulonglong2*)&edges_dup[k][r0 + 2];
            ulonglong2 A45 = *(const ulonglong2*)&edges_dup[k][r0 + 4];
            ulonglong2 A67 = *(const ulonglong2*)&edges_dup[k][r0 + 6];
            ulonglong2 B0  = *(const ulonglong2*)(wp + (size_t)k * 4096);
            ulonglong2 B1  = *(const ulonglong2*)(wp + (size_t)k * 4096 + 4);
            u64 ad[8] = {A01.x, A01.y, A23.x, A23.y, A45.x, A45.y, A67.x, A67.y};
            u64 bp[4] = {B0.x, B0.y, B1.x, B1.y};
            #pragma unroll
            for (int i = 0; i < 8; i++)
                #pragma unroll
                for (int j = 0; j < 4; j++)
                    acc[i][j] = ffma2(ad[i], bp[j], acc[i][j]);
        }

        // epilogue: relu(pre + b_e) * (mask*nodes), reduce 8x8 -> scalar
        int cglob = it * 256 + c0;
        int jcol  = c0 & 63;          // j within i-group (lane*8 mod 64)
        int ig    = cglob >> 6;       // output channel i (0..63)
        float4 bb0 = *(const float4*)(b_e + cglob);
        float4 bb1 = *(const float4*)(b_e + cglob + 4);
        float bb[8] = {bb0.x, bb0.y, bb0.z, bb0.w, bb1.x, bb1.y, bb1.z, bb1.w};
        float s = 0.0f;
        #pragma unroll
        for (int i = 0; i < 8; i++) {
            float4 w0 = *(const float4*)&wt_sh[r0 + i][jcol];
            float4 w1 = *(const float4*)&wt_sh[r0 + i][jcol + 4];
            float wv[8] = {w0.x, w0.y, w0.z, w0.w, w1.x, w1.y, w1.z, w1.w};
            #pragma unroll
            for (int j = 0; j < 4; j++) {
                float lo, hi;
                unpack2(acc[i][j], lo, hi);
                s = fmaf(fmaxf(lo + bb[2 * j],     0.0f), wv[2 * j],     s);
                s = fmaf(fmaxf(hi + bb[2 * j + 1], 0.0f), wv[2 * j + 1], s);
            }
        }
        s += __shfl_down_sync(0xffffffffu, s, 4, 8);
        s += __shfl_down_sync(0xffffffffu, s, 2, 8);
        s += __shfl_down_sync(0xffffffffu, s, 1, 8);
        if ((lane & 7) == 0) atomicAdd(&aggs[ig], s);
    }
    __syncthreads();   // aggs complete

    // ---- GRU tail ----
    if (t < 192) {
        float s = gbias[t];
        #pragma unroll 8
        for (int k = 0; k < 64; k++) s = fmaf(xrow[k], Kmat[k * 192 + t], s);
        xk1[t] = s;
    }
    __syncthreads();
    if (t < 64) {
        float bz = gbias[192 + t];
        float br = gbias[192 + 64 + t];
        float bh = gbias[192 + 128 + t];
        float z  = 1.0f / (1.0f + expf(-(xk1[t] + bz)));
        float r  = 1.0f / (1.0f + expf(-(xk1[64 + t] + br)));
        float hh = tanhf(xk1[128 + t] + r * bh);
        h1[t] = (1.0f - z) * hh;          // h was 0
    }
    __syncthreads();
    if (t < 192) {
        float s1 = gbias[t];
        float s2 = gbias[192 + t];
        #pragma unroll 8
        for (int k = 0; k < 64; k++) {
            s1 = fmaf(aggs[k], Kmat[k * 192 + t], s1);
            s2 = fmaf(h1[k],   Rmat[k * 192 + t], s2);
        }
        xk2[t] = s1; hk2[t] = s2;
    }
    __syncthreads();
    if (t < 64) {
        float z  = 1.0f / (1.0f + expf(-(xk2[t] + hk2[t])));
        float r  = 1.0f / (1.0f + expf(-(xk2[64 + t] + hk2[64 + t])));
        float hh = tanhf(xk2[128 + t] + r * hk2[128 + t]);
        out[((size_t)b * 64 + inode) * 64 + t] = z * h1[t] + (1.0f - z) * hh;
    }
}

extern "C" void kernel_launch(void* const* d_in, const int* in_sizes, int n_in,
                              void* d_out, int out_size) {
    const float* nodes = (const float*)d_in[0];
    const float* edges = (const float*)d_in[1];
    const float* mask  = (const float*)d_in[2];
    const float* W_e   = (const float*)d_in[3];
    const float* b_e   = (const float*)d_in[4];
    const float* gk    = (const float*)d_in[5];
    const float* gr    = (const float*)d_in[6];
    const float* gb    = (const float*)d_in[7];
    float* out = (float*)d_out;

    mp_fused_kernel<<<512, 256>>>(nodes, edges, mask, W_e, b_e, gk, gr, gb, out);
}